// round 8
// baseline (speedup 1.0000x reference)
#include <cuda_runtime.h>
#include <cstddef>

// ---------------------------------------------------------------------------
// Collapsed model (only pyramid level L-1 survives the reference):
//   g[b,f]    = (1/256) * sum over 16x16 patch grid of x   (f = c*256+pi*16+pj)
//   root[b,d] = sum_f W_emb[d,f]*g[b,f] + b_emb[d] + pos4[d]
//   out[b,o]  = sum_d W_cls[o,d]*root[b,d] + b_cls[o]
//
// Single persistent kernel, 192 blocks x 512 threads (all co-resident:
// launch_bounds(512,2) -> 296 slots >= 192), software grid barriers between
// the three phases.  Barrier counters are reset by the last block so every
// graph replay starts from the same state.
// ---------------------------------------------------------------------------

#define NB 192

__device__ float g_scratch[64 * 768];      // [b*3+c][256] == [b][768]
__device__ float root_scratch[64 * 128];
__device__ unsigned int bc1, bc2, bc3;     // arrive counters (zero-init)
__device__ unsigned int bf1, bf2;          // release flags   (zero-init)

__device__ __forceinline__ void grid_bar(unsigned int* cnt,
                                         volatile unsigned int* flag) {
    __syncthreads();
    if (threadIdx.x == 0) {
        __threadfence();                       // publish this block's writes
        if (atomicAdd(cnt, 1u) == NB - 1u) {
            *flag = 1u;                        // release
            __threadfence();
        } else {
            while (*flag == 0u) {}             // volatile -> L2 poll
        }
    }
    __syncthreads();
}

__global__ __launch_bounds__(512, 2) void fused(
    const float* __restrict__ x, const float* __restrict__ W_emb,
    const float* __restrict__ b_emb, const float* __restrict__ pos4,
    const float* __restrict__ W_cls, const float* __restrict__ b_cls,
    float* __restrict__ out) {
    const int bb = blockIdx.x;       // 0..191
    const int t = threadIdx.x;       // 0..511
    const int wid = t >> 5;
    const int lane = t & 31;

    __shared__ float smem[4 * 768];  // 12 KB, reused by phase 1 and phase 2

    // ===================== Phase 1: pooling (one plane/block) ==============
    {
        const int p = bb;            // plane = b*3 + c
        const float4* plane =
            reinterpret_cast<const float4*>(x + ((size_t)p << 16));

        float4 a0 = make_float4(0.f, 0.f, 0.f, 0.f);  // pi = (t>>6)
        float4 a1 = a0;                               // pi = (t>>6) + 8
#pragma unroll
        for (int k = 0; k < 32; k += 2) {
            float4 v0 = plane[t + 512 * k];
            float4 v1 = plane[t + 512 * (k + 1)];
            a0.x += v0.x; a0.y += v0.y; a0.z += v0.z; a0.w += v0.w;
            a1.x += v1.x; a1.y += v1.y; a1.z += v1.z; a1.w += v1.w;
        }
#pragma unroll
        for (int off = 4; off <= 16; off <<= 1) {
            a0.x += __shfl_xor_sync(0xffffffffu, a0.x, off);
            a0.y += __shfl_xor_sync(0xffffffffu, a0.y, off);
            a0.z += __shfl_xor_sync(0xffffffffu, a0.z, off);
            a0.w += __shfl_xor_sync(0xffffffffu, a0.w, off);
            a1.x += __shfl_xor_sync(0xffffffffu, a1.x, off);
            a1.y += __shfl_xor_sync(0xffffffffu, a1.y, off);
            a1.z += __shfl_xor_sync(0xffffffffu, a1.z, off);
            a1.w += __shfl_xor_sync(0xffffffffu, a1.w, off);
        }
        float4* spart = reinterpret_cast<float4*>(smem);  // [16][2][4]
        if (lane < 4) {
            spart[(wid * 2 + 0) * 4 + lane] = a0;
            spart[(wid * 2 + 1) * 4 + lane] = a1;
        }
        __syncthreads();
        if (t < 64) {
            const int pi = t >> 2;
            const int qq = t & 3;
            const int bw2 = (pi & 7) * 2;
            const int j = pi >> 3;
            float4 r0 = spart[((bw2 + 0) * 2 + j) * 4 + qq];
            float4 r1 = spart[((bw2 + 1) * 2 + j) * 4 + qq];
            const float sc = 1.0f / 256.0f;
            float4 o4 = make_float4((r0.x + r1.x) * sc, (r0.y + r1.y) * sc,
                                    (r0.z + r1.z) * sc, (r0.w + r1.w) * sc);
            reinterpret_cast<float4*>(g_scratch + p * 256 + pi * 16)[qq] = o4;
        }
        __syncthreads();   // spart reads done before smem reuse
    }

    grid_bar(&bc1, &bf1);

    // ===================== Phase 2: root = g @ W_emb^T + bias ==============
    if (bb < 128) {
        const int dt = bb & 7;       // d tile (16 d's)
        const int bt = bb >> 3;      // 0..15 (4 batches)

        // Stage g[bt*4 .. +3][768] in shared (768 float4 slots).
        float4* gs = reinterpret_cast<float4*>(smem);
        for (int s = t; s < 768; s += 512) {
            const int j = s / 192, off2 = s % 192;
            gs[s] = reinterpret_cast<const float4*>(
                        g_scratch + (bt * 4 + j) * 768)[off2];
        }
        __syncthreads();

        const int d = dt * 16 + wid;          // 16 warps -> 16 d's
        const float* wp = W_emb + d * 768 + lane;
        float a0 = 0.f, a1 = 0.f, a2 = 0.f, a3 = 0.f;
#pragma unroll
        for (int i = 0; i < 24; i++) {
            const float w = wp[i * 32];
            const int idx = lane + 32 * i;
            a0 += w * smem[0 * 768 + idx];
            a1 += w * smem[1 * 768 + idx];
            a2 += w * smem[2 * 768 + idx];
            a3 += w * smem[3 * 768 + idx];
        }
#pragma unroll
        for (int off = 16; off >= 1; off >>= 1) {
            a0 += __shfl_xor_sync(0xffffffffu, a0, off);
            a1 += __shfl_xor_sync(0xffffffffu, a1, off);
            a2 += __shfl_xor_sync(0xffffffffu, a2, off);
            a3 += __shfl_xor_sync(0xffffffffu, a3, off);
        }
        if (lane == 0) {
            const float bias = b_emb[d] + pos4[d];
            root_scratch[(bt * 4 + 0) * 128 + d] = a0 + bias;
            root_scratch[(bt * 4 + 1) * 128 + d] = a1 + bias;
            root_scratch[(bt * 4 + 2) * 128 + d] = a2 + bias;
            root_scratch[(bt * 4 + 3) * 128 + d] = a3 + bias;
        }
    } else {
        // Idle blocks warm L2 with W_cls (512 KB = 4096 x 128B lines).
        const int line = (bb - 128) * 512 + t;
        if (line < 4096) {
            const float* p = W_cls + line * 32;
            asm volatile("prefetch.global.L2 [%0];" :: "l"(p));
        }
    }

    grid_bar(&bc2, &bf2);

    // ===================== Phase 3: logits ================================
    {
        const int ot = bb >> 3;      // 0..23, o range [ot*42, ot*42+42)
        const int bt = bb & 7;       // 8 batches

        float rreg[8][4];
#pragma unroll
        for (int j = 0; j < 8; j++) {
            const float* rp = root_scratch + (bt * 8 + j) * 128 + lane;
#pragma unroll
            for (int i = 0; i < 4; i++) rreg[j][i] = rp[i * 32];
        }

#pragma unroll
        for (int jj = 0; jj < 3; jj++) {
            const int k = wid * 3 + jj;            // 0..47
            const int o = ot * 42 + k;
            if (k < 42 && o < 1000) {
                const float* wp = W_cls + o * 128 + lane;
                float acc[8];
#pragma unroll
                for (int j = 0; j < 8; j++) acc[j] = 0.f;
#pragma unroll
                for (int i = 0; i < 4; i++) {
                    const float w = wp[i * 32];
#pragma unroll
                    for (int j = 0; j < 8; j++) acc[j] += w * rreg[j][i];
                }
#pragma unroll
                for (int off = 16; off >= 1; off >>= 1) {
#pragma unroll
                    for (int j = 0; j < 8; j++)
                        acc[j] += __shfl_xor_sync(0xffffffffu, acc[j], off);
                }
                if (lane == 0) {
                    const float bc = b_cls[o];
#pragma unroll
                    for (int j = 0; j < 8; j++)
                        out[(bt * 8 + j) * 1000 + o] = acc[j] + bc;
                }
            }
        }
    }

    // ===================== Reset barrier state for next replay =============
    __syncthreads();
    if (t == 0) {
        __threadfence();
        if (atomicAdd(&bc3, 1u) == NB - 1u) {
            bc1 = 0u; bf1 = 0u; bc2 = 0u; bf2 = 0u;
            __threadfence();
            bc3 = 0u;
        }
    }
}

// ---------------------------------------------------------------------------
// Inputs (metadata order): 0:x 1:W_emb 2:b_emb 3:pos0 4:pos1 5:pos2 6:pos3
//                          7:pos4 8:W_cls 9:b_cls.  Output: (64,1000) f32.
// ---------------------------------------------------------------------------
extern "C" void kernel_launch(void* const* d_in, const int* in_sizes, int n_in,
                              void* d_out, int out_size) {
    const float* x     = (const float*)d_in[0];
    const float* W_emb = (const float*)d_in[1];
    const float* b_emb = (const float*)d_in[2];
    const float* pos4  = (const float*)d_in[7];
    const float* W_cls = (const float*)d_in[8];
    const float* b_cls = (const float*)d_in[9];
    float* out = (float*)d_out;

    fused<<<NB, 512>>>(x, W_emb, b_emb, pos4, W_cls, b_cls, out);
}